// round 4
// baseline (speedup 1.0000x reference)
#include <cuda_runtime.h>
#include <cstddef>

// Problem constants
#define VSZ   100000
#define DIM   256
#define NSEQ  8192
#define SLEN  20
#define HID   256
#define G4    1024           // 4*H
#define KTOT  512            // D + H

// ---------------------------------------------------------------------------
// Scratch (device globals only — no allocations allowed)
// ---------------------------------------------------------------------------
__device__ __align__(256) float g_Wt[2 * KTOT * G4];        // [dir][k][g]  4 MB
__device__ __align__(256) float g_h[2 * NSEQ * HID];        // hidden state 16.8 MB
__device__ __align__(256) float g_c[2 * NSEQ * HID];        // cell state   16.8 MB
__device__ __align__(256) float g_gates[2 * (size_t)NSEQ * G4]; // 67 MB
__device__ __align__(256) float g_acc[NSEQ];
__device__ int g_is64;

// ---------------------------------------------------------------------------
// Detect neigh_idx dtype (int32 vs int64). For genuine int64 data all values
// lie in [0, VSZ). int32 data read as int64 combines adjacent words and is
// >= 2^32 unless the odd word is exactly 0 (prob ~1e-5 per sample).
// Deterministic: same input -> same flag.
// ---------------------------------------------------------------------------
__global__ void detect_idx_kernel(const void* neigh) {
    const long long* p = (const long long*)neigh;
    int ok = 1;
    #pragma unroll
    for (int i = 0; i < 4; i++) {
        long long v = p[i];
        if (v < 0 || v >= (long long)VSZ) ok = 0;
    }
    g_is64 = ok;
}

// ---------------------------------------------------------------------------
// Zero h, c, acc
// ---------------------------------------------------------------------------
__global__ void prep_state_kernel() {
    int i = blockIdx.x * blockDim.x + threadIdx.x;
    int tot = 2 * NSEQ * HID;
    if (i < tot) { g_h[i] = 0.0f; g_c[i] = 0.0f; }
    if (i < NSEQ) g_acc[i] = 0.0f;
}

// ---------------------------------------------------------------------------
// Build Wt[dir][k][g]:  k < DIM -> w_ih[g][k],  else -> w_hh[g][k-DIM]
// (one-time 4MB transpose per launch; L2-bound, negligible)
// ---------------------------------------------------------------------------
__global__ void prep_weights_kernel(const float* __restrict__ wihf,
                                    const float* __restrict__ whhf,
                                    const float* __restrict__ wihb,
                                    const float* __restrict__ whhb) {
    int i = blockIdx.x * blockDim.x + threadIdx.x;
    if (i >= 2 * KTOT * G4) return;
    int dir = i / (KTOT * G4);
    int rem = i % (KTOT * G4);
    int k = rem / G4;
    int g = rem % G4;
    const float* wih = dir ? wihb : wihf;
    const float* whh = dir ? whhb : whhf;
    float v = (k < DIM) ? wih[g * DIM + k] : whh[g * HID + (k - DIM)];
    g_Wt[i] = v;
}

// ---------------------------------------------------------------------------
// Step GEMM: gates[dir][n][g] = sum_k A[n][k] * Wt[dir][k][g]
//   A[n][k] = k < DIM ? emb[idx(n, t_x)][k] : h[dir][n][k-DIM]
// Classic 128x128x8 SGEMM, 256 threads, 8x8 microtile, fused gather.
// ---------------------------------------------------------------------------
#define BM 128
#define BN 128
#define BK 8
#define TM 8
#define TN 8

__global__ __launch_bounds__(256, 2)
void lstm_gemm_kernel(const float* __restrict__ emb,
                      const void*  __restrict__ neigh,
                      int t) {
    const int dir = blockIdx.z;
    const int t_x = dir ? (SLEN - 1 - t) : t;

    __shared__ float As[BK][BM];
    __shared__ float Bs[BK][BN];

    const int tid = threadIdx.x;
    const int blockRow = blockIdx.y;
    const int blockCol = blockIdx.x;

    // A loader: each thread owns one row/float4 slot (128 rows * 2 float4)
    const int aRow  = tid >> 1;          // 0..127
    const int aCol4 = (tid & 1) * 4;     // 0 or 4
    const int n = blockRow * BM + aRow;

    long long idx;
    if (g_is64) idx = ((const long long*)neigh)[(long long)n * SLEN + t_x];
    else        idx = ((const int*)neigh)[n * SLEN + t_x];
    const float* aEmb = emb + (long long)idx * DIM;
    const float* aH   = g_h + ((size_t)dir * NSEQ + n) * HID;

    // B loader: 8 rows * 32 float4
    const int bRow  = tid >> 5;          // 0..7
    const int bCol4 = (tid & 31) * 4;    // 0..124
    const float* Wt = g_Wt + (size_t)dir * (KTOT * G4) + blockCol * BN;

    const int tr = tid >> 4;             // 0..15
    const int tc = tid & 15;             // 0..15

    float accv[TM][TN] = {};
    float regM[TM], regN[TN];

    for (int k0 = 0; k0 < KTOT; k0 += BK) {
        const int kA = k0 + aCol4;
        float4 av = (kA < DIM) ? *(const float4*)(aEmb + kA)
                               : *(const float4*)(aH + (kA - DIM));
        As[aCol4 + 0][aRow] = av.x;
        As[aCol4 + 1][aRow] = av.y;
        As[aCol4 + 2][aRow] = av.z;
        As[aCol4 + 3][aRow] = av.w;

        float4 bv = *(const float4*)(Wt + (size_t)(k0 + bRow) * G4 + bCol4);
        *(float4*)&Bs[bRow][bCol4] = bv;
        __syncthreads();

        #pragma unroll
        for (int k = 0; k < BK; k++) {
            #pragma unroll
            for (int m = 0; m < TM; m++) regM[m] = As[k][tr * TM + m];
            #pragma unroll
            for (int q = 0; q < TN; q++) regN[q] = Bs[k][tc * TN + q];
            #pragma unroll
            for (int m = 0; m < TM; m++)
                #pragma unroll
                for (int q = 0; q < TN; q++)
                    accv[m][q] += regM[m] * regN[q];
        }
        __syncthreads();
    }

    float* out = g_gates + (size_t)dir * NSEQ * G4
               + (size_t)(blockRow * BM + tr * TM) * G4
               + blockCol * BN + tc * TN;
    #pragma unroll
    for (int m = 0; m < TM; m++) {
        float4 v0 = make_float4(accv[m][0], accv[m][1], accv[m][2], accv[m][3]);
        float4 v1 = make_float4(accv[m][4], accv[m][5], accv[m][6], accv[m][7]);
        *(float4*)(out + (size_t)m * G4)     = v0;
        *(float4*)(out + (size_t)m * G4 + 4) = v1;
    }
}

// ---------------------------------------------------------------------------
// Pointwise gates + state update + per-sequence accumulation.
// One block per sequence, 256 threads (one per hidden unit), both directions.
// PyTorch gate order: i, f, g, o.
// ---------------------------------------------------------------------------
__global__ __launch_bounds__(256)
void lstm_point_kernel(const float* __restrict__ bf,
                       const float* __restrict__ bb) {
    const int n = blockIdx.x;
    const int j = threadIdx.x;
    float s_local = 0.0f;

    #pragma unroll
    for (int dir = 0; dir < 2; dir++) {
        const float* b = dir ? bb : bf;
        const float* g = g_gates + (size_t)dir * NSEQ * G4 + (size_t)n * G4;
        float gi = g[j]           + b[j];
        float gf = g[j + 256]     + b[j + 256];
        float gg = g[j + 512]     + b[j + 512];
        float go = g[j + 768]     + b[j + 768];
        size_t hidx = (size_t)dir * NSEQ * HID + (size_t)n * HID + j;
        float c = g_c[hidx];
        float si = 1.0f / (1.0f + __expf(-gi));
        float sf = 1.0f / (1.0f + __expf(-gf));
        float so = 1.0f / (1.0f + __expf(-go));
        float cn = sf * c + si * tanhf(gg);
        float hn = so * tanhf(cn);
        g_c[hidx] = cn;
        g_h[hidx] = hn;
        s_local += hn;
    }

    __shared__ float red[256];
    red[j] = s_local;
    __syncthreads();
    #pragma unroll
    for (int st = 128; st > 0; st >>= 1) {
        if (j < st) red[j] += red[j + st];
        __syncthreads();
    }
    if (j == 0) g_acc[n] += red[0];
}

// ---------------------------------------------------------------------------
// out[n][j] = acc[n] / (2H)   for all j in [0, 2H)
// ---------------------------------------------------------------------------
__global__ void final_kernel(float* __restrict__ out) {
    int i = blockIdx.x * blockDim.x + threadIdx.x;
    if (i < NSEQ * 512) out[i] = g_acc[i >> 9] * (1.0f / 512.0f);
}

// ---------------------------------------------------------------------------
// Launch
// ---------------------------------------------------------------------------
extern "C" void kernel_launch(void* const* d_in, const int* in_sizes, int n_in,
                              void* d_out, int out_size) {
    const float* emb   = (const float*)d_in[0];
    const float* wih_f = (const float*)d_in[1];
    const float* whh_f = (const float*)d_in[2];
    const float* b_f   = (const float*)d_in[3];
    const float* wih_b = (const float*)d_in[4];
    const float* whh_b = (const float*)d_in[5];
    const float* b_b   = (const float*)d_in[6];
    const void*  neigh = d_in[7];
    float* out = (float*)d_out;

    detect_idx_kernel<<<1, 1>>>(neigh);

    {
        int tot = 2 * NSEQ * HID;
        prep_state_kernel<<<(tot + 255) / 256, 256>>>();
    }
    {
        int tot = 2 * KTOT * G4;
        prep_weights_kernel<<<(tot + 255) / 256, 256>>>(wih_f, whh_f, wih_b, whh_b);
    }

    dim3 gemm_grid(G4 / BN, NSEQ / BM, 2);   // (8, 64, 2)
    for (int t = 0; t < SLEN; t++) {
        lstm_gemm_kernel<<<gemm_grid, 256>>>(emb, neigh, t);
        lstm_point_kernel<<<NSEQ, 256>>>(b_f, b_b);
    }

    final_kernel<<<(NSEQ * 512 + 255) / 256, 256>>>(out);
}

// round 6
// speedup vs baseline: 2.3769x; 2.3769x over previous
#include <cuda_runtime.h>
#include <cuda_fp16.h>
#include <cstdint>
#include <cstddef>

#define VSZ   100000
#define DIM   256
#define NSEQ  8192
#define SLEN  20
#define HID   256
#define G4    1024
#define KTOT  512

// ---------------------------------------------------------------------------
// Device globals (no allocations allowed). fp16 data packed as u32 (2 halves,
// k-consecutive). hi/lo planes give ~fp32 accuracy via 3-product split mma.
// ---------------------------------------------------------------------------
__device__ __align__(256) unsigned g_Ehi[(size_t)VSZ * 128];     // 51.2 MB
__device__ __align__(256) unsigned g_Elo[(size_t)VSZ * 128];     // 51.2 MB
__device__ __align__(256) unsigned g_Whi[2 * 1024 * 256];        // [dir][g][kpair]
__device__ __align__(256) unsigned g_Wlo[2 * 1024 * 256];
__device__ __align__(256) unsigned g_Hhi[2 * NSEQ * 128];
__device__ __align__(256) unsigned g_Hlo[2 * NSEQ * 128];
__device__ __align__(256) float    g_c[2 * NSEQ * HID];
__device__ __align__(256) float    g_gates[2 * (size_t)NSEQ * G4];
__device__ __align__(256) float    g_acc[NSEQ];
__device__ int g_is64;

// ---------------------------------------------------------------------------
__device__ __forceinline__ unsigned pack_split(float a, float b, unsigned& lo) {
    __half ha = __float2half_rn(a), hb = __float2half_rn(b);
    __half la = __float2half_rn(a - __half2float(ha));
    __half lb = __float2half_rn(b - __half2float(hb));
    lo = (unsigned)__half_as_ushort(la) | ((unsigned)__half_as_ushort(lb) << 16);
    return (unsigned)__half_as_ushort(ha) | ((unsigned)__half_as_ushort(hb) << 16);
}

__device__ __forceinline__ uint32_t smem_u32(const void* p) {
    uint32_t a;
    asm("{ .reg .u64 t; cvta.to.shared.u64 t, %1; cvt.u32.u64 %0, t; }" : "=r"(a) : "l"(p));
    return a;
}

__device__ __forceinline__ void cpasync16(uint32_t dst, const void* src) {
    asm volatile("cp.async.cg.shared.global [%0],[%1],16;" :: "r"(dst), "l"(src));
}

#define LDSM4(r, addr) asm volatile( \
    "ldmatrix.sync.aligned.m8n8.x4.shared.b16 {%0,%1,%2,%3},[%4];" \
    : "=r"((r)[0]), "=r"((r)[1]), "=r"((r)[2]), "=r"((r)[3]) : "r"(addr))

#define MMA(d, a, b0, b1) asm volatile( \
    "mma.sync.aligned.m16n8k16.row.col.f32.f16.f16.f32 " \
    "{%0,%1,%2,%3},{%4,%5,%6,%7},{%8,%9},{%0,%1,%2,%3};" \
    : "+f"((d)[0]), "+f"((d)[1]), "+f"((d)[2]), "+f"((d)[3]) \
    : "r"((a)[0]), "r"((a)[1]), "r"((a)[2]), "r"((a)[3]), "r"(b0), "r"(b1))

// ---------------------------------------------------------------------------
__global__ void detect_idx_kernel(const void* neigh) {
    const long long* p = (const long long*)neigh;
    int ok = 1;
    #pragma unroll
    for (int i = 0; i < 4; i++) {
        long long v = p[i];
        if (v < 0 || v >= (long long)VSZ) ok = 0;
    }
    g_is64 = ok;
}

__global__ void prep_emb_kernel(const float* __restrict__ emb) {
    size_t i = (size_t)blockIdx.x * blockDim.x + threadIdx.x;
    if (i >= (size_t)VSZ * 128) return;
    size_t v = i >> 7;
    int p = (int)(i & 127);
    unsigned lo;
    unsigned hi = pack_split(emb[v * 256 + 2 * p], emb[v * 256 + 2 * p + 1], lo);
    g_Ehi[i] = hi;
    g_Elo[i] = lo;
}

// W layout [dir][g][kpair]: k<256 -> w_ih[g][k], else w_hh[g][k-256]
__global__ void prep_w_kernel(const float* __restrict__ wihf,
                              const float* __restrict__ whhf,
                              const float* __restrict__ wihb,
                              const float* __restrict__ whhb) {
    int i = blockIdx.x * blockDim.x + threadIdx.x;
    if (i >= 2 * 1024 * 256) return;
    int d = i / (1024 * 256);
    int rem = i % (1024 * 256);
    int g = rem >> 8;
    int p = rem & 255;
    const float* wih = d ? wihb : wihf;
    const float* whh = d ? whhb : whhf;
    int k0 = 2 * p, k1 = 2 * p + 1;
    float a = (k0 < 256) ? wih[g * 256 + k0] : whh[g * 256 + k0 - 256];
    float b = (k1 < 256) ? wih[g * 256 + k1] : whh[g * 256 + k1 - 256];
    unsigned lo;
    unsigned hi = pack_split(a, b, lo);
    g_Whi[i] = hi;
    g_Wlo[i] = lo;
}

__global__ void prep_state_kernel() {
    int i = blockIdx.x * blockDim.x + threadIdx.x;
    if (i < 2 * NSEQ * 128) { g_Hhi[i] = 0u; g_Hlo[i] = 0u; }
    if (i < 2 * NSEQ * HID) g_c[i] = 0.0f;
    if (i < NSEQ)           g_acc[i] = 0.0f;
}

// ---------------------------------------------------------------------------
// Step GEMM: gates[dir][n][g] = sum_k A[n][k]*W[g][k]
// A = [gathered emb | h] fp16 hi/lo. 128x128 tile, 8 warps of 64x32.
// 16 k-chunks of 32 halves, cp.async double buffered, ldmatrix.x4.
// smem plane = 128 rows * 20 words (16 payload + 4 pad, ldmatrix conflict-free)
// buffer = Ahi|Alo|Bhi|Blo planes (10240 words); two buffers = 81920 bytes.
// ---------------------------------------------------------------------------
__global__ __launch_bounds__(256)
void lstm_step_gemm(const void* __restrict__ neigh, int t) {
    extern __shared__ unsigned sm[];
    const uint32_t smb = smem_u32(sm);

    const int tid = threadIdx.x, lane = tid & 31, warp = tid >> 5;
    const int wr = warp >> 2, wc = warp & 3;
    const int bx = blockIdx.x, by = blockIdx.y, dir = blockIdx.z;
    const int t_x = dir ? (SLEN - 1 - t) : t;

    // loader geometry: thread owns rows (lrow, lrow+64), one 16B seg
    const int lrow = tid >> 2;
    const int lseg = tid & 3;
    const int n0 = by * 128 + lrow, n1 = n0 + 64;

    long long i0, i1;
    if (g_is64) {
        i0 = ((const long long*)neigh)[(long long)n0 * SLEN + t_x];
        i1 = ((const long long*)neigh)[(long long)n1 * SLEN + t_x];
    } else {
        i0 = ((const int*)neigh)[n0 * SLEN + t_x];
        i1 = ((const int*)neigh)[n1 * SLEN + t_x];
    }
    const unsigned* e0h = g_Ehi + (size_t)i0 * 128;
    const unsigned* e1h = g_Ehi + (size_t)i1 * 128;
    const unsigned* e0l = g_Elo + (size_t)i0 * 128;
    const unsigned* e1l = g_Elo + (size_t)i1 * 128;
    const unsigned* h0h = g_Hhi + ((size_t)dir * NSEQ + n0) * 128;
    const unsigned* h1h = g_Hhi + ((size_t)dir * NSEQ + n1) * 128;
    const unsigned* h0l = g_Hlo + ((size_t)dir * NSEQ + n0) * 128;
    const unsigned* h1l = g_Hlo + ((size_t)dir * NSEQ + n1) * 128;
    const unsigned* w0h = g_Whi + ((size_t)dir * 1024 + bx * 128 + lrow) * 256;
    const unsigned* w1h = w0h + 64 * 256;
    const unsigned* w0l = g_Wlo + ((size_t)dir * 1024 + bx * 128 + lrow) * 256;
    const unsigned* w1l = w0l + 64 * 256;

    const uint32_t dA0 = (uint32_t)(lrow * 20 + lseg * 4) * 4;  // bytes
    const uint32_t dA1 = dA0 + 64 * 80;

    // ldmatrix lane byte-offsets within a plane
    const uint32_t aLane = (uint32_t)((lane & 15) * 80 + (lane >> 4) * 16);
    const uint32_t bLane = (uint32_t)(((lane & 7) + ((lane >> 4) << 3)) * 80
                                      + (((lane >> 3) & 1) << 4));

    float acc[4][4][4] = {};

    auto load_chunk = [&](int kc, int buf) {
        uint32_t base = smb + (uint32_t)buf * 40960u;
        int kp = kc * 16 + lseg * 4;
        const unsigned *a0h, *a1h, *a0l, *a1l;
        if (kc < 8) { a0h = e0h + kp; a1h = e1h + kp; a0l = e0l + kp; a1l = e1l + kp; }
        else { int q = kp - 128; a0h = h0h + q; a1h = h1h + q; a0l = h0l + q; a1l = h1l + q; }
        cpasync16(base + dA0, a0h);
        cpasync16(base + dA1, a1h);
        cpasync16(base + 10240u + dA0, a0l);
        cpasync16(base + 10240u + dA1, a1l);
        cpasync16(base + 20480u + dA0, w0h + kp);
        cpasync16(base + 20480u + dA1, w1h + kp);
        cpasync16(base + 30720u + dA0, w0l + kp);
        cpasync16(base + 30720u + dA1, w1l + kp);
        asm volatile("cp.async.commit_group;");
    };

    auto compute_chunk = [&](int buf) {
        uint32_t base = smb + (uint32_t)buf * 40960u;
        #pragma unroll
        for (int ks = 0; ks < 2; ks++) {
            uint32_t koff = (uint32_t)ks * 32;
            uint32_t ah[4][4], al[4][4], bh[2][4], bl[2][4];
            #pragma unroll
            for (int mi = 0; mi < 4; mi++) {
                uint32_t ra = base + (uint32_t)(wr * 64 + mi * 16) * 80 + aLane + koff;
                LDSM4(ah[mi], ra);
                LDSM4(al[mi], ra + 10240u);
            }
            #pragma unroll
            for (int np = 0; np < 2; np++) {
                uint32_t rb = base + 20480u + (uint32_t)(wc * 32 + np * 16) * 80 + bLane + koff;
                LDSM4(bh[np], rb);
                LDSM4(bl[np], rb + 10240u);
            }
            #pragma unroll
            for (int mi = 0; mi < 4; mi++)
                #pragma unroll
                for (int ni = 0; ni < 4; ni++) {
                    const int np = ni >> 1, s = (ni & 1) * 2;
                    MMA(acc[mi][ni], ah[mi], bh[np][s], bh[np][s + 1]);
                    MMA(acc[mi][ni], ah[mi], bl[np][s], bl[np][s + 1]);
                    MMA(acc[mi][ni], al[mi], bh[np][s], bh[np][s + 1]);
                }
        }
    };

    load_chunk(0, 0);
    #pragma unroll 1
    for (int kc = 0; kc < 16; kc++) {
        if (kc < 15) {
            load_chunk(kc + 1, (kc + 1) & 1);
            asm volatile("cp.async.wait_group 1;");
        } else {
            asm volatile("cp.async.wait_group 0;");
        }
        __syncthreads();
        compute_chunk(kc & 1);
        __syncthreads();
    }

    // epilogue: write gate pre-activations fp32
    float* outg = g_gates + (size_t)dir * NSEQ * G4;
    #pragma unroll
    for (int mi = 0; mi < 4; mi++) {
        const int r0 = by * 128 + wr * 64 + mi * 16 + (lane >> 2);
        #pragma unroll
        for (int ni = 0; ni < 4; ni++) {
            const int g = bx * 128 + wc * 32 + ni * 8 + (lane & 3) * 2;
            float2 v0 = make_float2(acc[mi][ni][0], acc[mi][ni][1]);
            float2 v1 = make_float2(acc[mi][ni][2], acc[mi][ni][3]);
            *(float2*)(outg + (size_t)r0 * G4 + g)       = v0;
            *(float2*)(outg + (size_t)(r0 + 8) * G4 + g) = v1;
        }
    }
}

// ---------------------------------------------------------------------------
// Pointwise: threads 0-127 dir0, 128-255 dir1; each owns units 2j, 2j+1
// so it can split-pack the h word it owns. PyTorch gate order i,f,g,o.
// ---------------------------------------------------------------------------
__global__ __launch_bounds__(256)
void lstm_point_kernel(const float* __restrict__ bf,
                       const float* __restrict__ bb) {
    const int n = blockIdx.x;
    const int tid = threadIdx.x;
    const int dir = tid >> 7;
    const int j = tid & 127;
    const float* b = dir ? bb : bf;
    const float* g = g_gates + (size_t)dir * NSEQ * G4 + (size_t)n * G4;
    const size_t cb = (size_t)dir * NSEQ * HID + (size_t)n * HID;

    float s_local = 0.0f, hn2[2];
    #pragma unroll
    for (int u2 = 0; u2 < 2; u2++) {
        int u = 2 * j + u2;
        float gi = g[u]       + b[u];
        float gf = g[256 + u] + b[256 + u];
        float gg = g[512 + u] + b[512 + u];
        float go = g[768 + u] + b[768 + u];
        float c = g_c[cb + u];
        float si = 1.0f / (1.0f + __expf(-gi));
        float sf = 1.0f / (1.0f + __expf(-gf));
        float so = 1.0f / (1.0f + __expf(-go));
        float cn = sf * c + si * tanhf(gg);
        float hn = so * tanhf(cn);
        g_c[cb + u] = cn;
        hn2[u2] = hn;
        s_local += hn;
    }
    unsigned lo;
    unsigned hi = pack_split(hn2[0], hn2[1], lo);
    g_Hhi[((size_t)dir * NSEQ + n) * 128 + j] = hi;
    g_Hlo[((size_t)dir * NSEQ + n) * 128 + j] = lo;

    __shared__ float red[256];
    red[tid] = s_local;
    __syncthreads();
    #pragma unroll
    for (int st = 128; st > 0; st >>= 1) {
        if (tid < st) red[tid] += red[tid + st];
        __syncthreads();
    }
    if (tid == 0) g_acc[n] += red[0];
}

__global__ void final_kernel(float* __restrict__ out) {
    int i = blockIdx.x * blockDim.x + threadIdx.x;
    if (i < NSEQ * 512) out[i] = g_acc[i >> 9] * (1.0f / 512.0f);
}

// ---------------------------------------------------------------------------
extern "C" void kernel_launch(void* const* d_in, const int* in_sizes, int n_in,
                              void* d_out, int out_size) {
    const float* emb   = (const float*)d_in[0];
    const float* wih_f = (const float*)d_in[1];
    const float* whh_f = (const float*)d_in[2];
    const float* b_f   = (const float*)d_in[3];
    const float* wih_b = (const float*)d_in[4];
    const float* whh_b = (const float*)d_in[5];
    const float* b_b   = (const float*)d_in[6];
    const void*  neigh = d_in[7];
    float* out = (float*)d_out;

    cudaFuncSetAttribute(lstm_step_gemm,
                         cudaFuncAttributeMaxDynamicSharedMemorySize, 81920);

    detect_idx_kernel<<<1, 1>>>(neigh);
    {
        size_t tot = (size_t)VSZ * 128;
        prep_emb_kernel<<<(unsigned)((tot + 255) / 256), 256>>>(emb);
    }
    {
        int tot = 2 * 1024 * 256;
        prep_w_kernel<<<(tot + 255) / 256, 256>>>(wih_f, whh_f, wih_b, whh_b);
    }
    {
        int tot = 2 * NSEQ * HID;
        prep_state_kernel<<<(tot + 255) / 256, 256>>>();
    }

    dim3 gemm_grid(8, 64, 2);
    for (int t = 0; t < SLEN; t++) {
        lstm_step_gemm<<<gemm_grid, 256, 81920>>>(neigh, t);
        lstm_point_kernel<<<NSEQ, 256>>>(b_f, b_b);
    }

    final_kernel<<<(NSEQ * 512 + 255) / 256, 256>>>(out);
}

// round 7
// speedup vs baseline: 2.5586x; 1.0764x over previous
#include <cuda_runtime.h>
#include <cuda_fp16.h>
#include <cstdint>
#include <cstddef>

#define VSZ   100000
#define NSEQ  8192
#define SLEN  20

// ---------------------------------------------------------------------------
// Device globals. fp16 packed u32 (two k-consecutive halves); hi/lo planes
// give ~fp32 accuracy via 3-product split mma.
// Gate columns are INTERLEAVED: gcol = unit*4 + gate (i,f,g,o).
// ---------------------------------------------------------------------------
__device__ __align__(256) unsigned g_Ehi[(size_t)VSZ * 128];
__device__ __align__(256) unsigned g_Elo[(size_t)VSZ * 128];
__device__ __align__(256) unsigned g_WihHi[2048 * 128];   // [dir*1024+gcol][kpair]
__device__ __align__(256) unsigned g_WihLo[2048 * 128];
__device__ __align__(256) unsigned g_WhhHi[2048 * 128];
__device__ __align__(256) unsigned g_WhhLo[2048 * 128];
__device__ __align__(256) unsigned g_Hhi[2 * NSEQ * 128];
__device__ __align__(256) unsigned g_Hlo[2 * NSEQ * 128];
__device__ __align__(256) float    g_c[2 * NSEQ * 256];
__device__ __align__(256) float    g_XG[(size_t)2 * VSZ * 1024];  // 819 MB
__device__ __align__(256) float    g_biasI[2048];
__device__ __align__(256) float    g_part[16 * NSEQ];
__device__ __align__(256) float    g_acc[NSEQ];
__device__ int g_is64;

// ---------------------------------------------------------------------------
__device__ __forceinline__ unsigned pack_split(float a, float b, unsigned& lo) {
    __half ha = __float2half_rn(a), hb = __float2half_rn(b);
    __half la = __float2half_rn(a - __half2float(ha));
    __half lb = __float2half_rn(b - __half2float(hb));
    lo = (unsigned)__half_as_ushort(la) | ((unsigned)__half_as_ushort(lb) << 16);
    return (unsigned)__half_as_ushort(ha) | ((unsigned)__half_as_ushort(hb) << 16);
}

__device__ __forceinline__ uint32_t smem_u32(const void* p) {
    uint32_t a;
    asm("{ .reg .u64 t; cvta.to.shared.u64 t, %1; cvt.u32.u64 %0, t; }" : "=r"(a) : "l"(p));
    return a;
}

__device__ __forceinline__ void cpasync16(uint32_t dst, const void* src) {
    asm volatile("cp.async.cg.shared.global [%0],[%1],16;" :: "r"(dst), "l"(src));
}

#define LDSM4(r, addr) asm volatile( \
    "ldmatrix.sync.aligned.m8n8.x4.shared.b16 {%0,%1,%2,%3},[%4];" \
    : "=r"((r)[0]), "=r"((r)[1]), "=r"((r)[2]), "=r"((r)[3]) : "r"(addr))

#define MMA(d, a, b0, b1) asm volatile( \
    "mma.sync.aligned.m16n8k16.row.col.f32.f16.f16.f32 " \
    "{%0,%1,%2,%3},{%4,%5,%6,%7},{%8,%9},{%0,%1,%2,%3};" \
    : "+f"((d)[0]), "+f"((d)[1]), "+f"((d)[2]), "+f"((d)[3]) \
    : "r"((a)[0]), "r"((a)[1]), "r"((a)[2]), "r"((a)[3]), "r"(b0), "r"(b1))

// ---------------------------------------------------------------------------
__global__ void detect_idx_kernel(const void* neigh) {
    const long long* p = (const long long*)neigh;
    int ok = 1;
    #pragma unroll
    for (int i = 0; i < 4; i++) {
        long long v = p[i];
        if (v < 0 || v >= (long long)VSZ) ok = 0;
    }
    g_is64 = ok;
}

__global__ void prep_emb_kernel(const float* __restrict__ emb) {
    size_t i = (size_t)blockIdx.x * blockDim.x + threadIdx.x;
    if (i >= (size_t)VSZ * 128) return;
    size_t v = i >> 7;
    int p = (int)(i & 127);
    unsigned lo;
    unsigned hi = pack_split(emb[v * 256 + 2 * p], emb[v * 256 + 2 * p + 1], lo);
    g_Ehi[i] = hi;
    g_Elo[i] = lo;
}

// Interleaved weight split: row dirgcol = dir*1024 + (unit*4+gate); orig row
// of the torch weight = gate*256 + unit; K halves paired.
__global__ void prep_w_kernel(const float* __restrict__ wihf,
                              const float* __restrict__ whhf,
                              const float* __restrict__ wihb,
                              const float* __restrict__ whhb) {
    int i = blockIdx.x * blockDim.x + threadIdx.x;
    if (i >= 2048 * 128) return;
    int dirgcol = i >> 7, kp = i & 127;
    int dir = dirgcol >> 10, gcol = dirgcol & 1023;
    int orow = (gcol & 3) * 256 + (gcol >> 2);
    const float* wih = dir ? wihb : wihf;
    const float* whh = dir ? whhb : whhf;
    unsigned lo, hi;
    hi = pack_split(wih[orow * 256 + 2 * kp], wih[orow * 256 + 2 * kp + 1], lo);
    g_WihHi[i] = hi; g_WihLo[i] = lo;
    hi = pack_split(whh[orow * 256 + 2 * kp], whh[orow * 256 + 2 * kp + 1], lo);
    g_WhhHi[i] = hi; g_WhhLo[i] = lo;
}

__global__ void prep_state_kernel(const float* __restrict__ bf,
                                  const float* __restrict__ bb) {
    int i = blockIdx.x * blockDim.x + threadIdx.x;
    if (i < 2 * NSEQ * 128) { g_Hhi[i] = 0u; g_Hlo[i] = 0u; }
    if (i < 2 * NSEQ * 256) g_c[i] = 0.0f;
    if (i < 16 * NSEQ)      g_part[i] = 0.0f;
    if (i < 2048) {
        int dir = i >> 10, gcol = i & 1023;
        const float* b = dir ? bb : bf;
        g_biasI[i] = b[(gcol & 3) * 256 + (gcol >> 2)];
    }
}

// ---------------------------------------------------------------------------
// Vocab GEMM: XG[dir][v][gcol] = sum_k emb[v][k] * Wih[dir][gcol][k]
// 128x128 tile, K=256 (8 chunks of 32 halves), cp.async double buffered.
// smem plane = 128 rows * 20 u32 (16 payload + 4 pad). 2 buffers x 4 planes.
// ---------------------------------------------------------------------------
__global__ __launch_bounds__(256)
void vocab_gemm_kernel() {
    extern __shared__ unsigned sm[];
    const uint32_t smb = smem_u32(sm);
    const int tid = threadIdx.x, lane = tid & 31, warp = tid >> 5;
    const int wr = warp >> 2, wc = warp & 3;
    const int bx = blockIdx.x, by = blockIdx.y;

    const int lrow = tid >> 2, lseg = tid & 3;
    int v0 = by * 128 + lrow, v1 = v0 + 64;
    int v0c = v0 < VSZ ? v0 : VSZ - 1;
    int v1c = v1 < VSZ ? v1 : VSZ - 1;
    const unsigned* a0h = g_Ehi + (size_t)v0c * 128;
    const unsigned* a1h = g_Ehi + (size_t)v1c * 128;
    const unsigned* a0l = g_Elo + (size_t)v0c * 128;
    const unsigned* a1l = g_Elo + (size_t)v1c * 128;
    const unsigned* b0h = g_WihHi + (size_t)(bx * 128 + lrow) * 128;
    const unsigned* b1h = b0h + 64 * 128;
    const unsigned* b0l = g_WihLo + (size_t)(bx * 128 + lrow) * 128;
    const unsigned* b1l = b0l + 64 * 128;

    const uint32_t dA0 = (uint32_t)(lrow * 20 + lseg * 4) * 4;
    const uint32_t dA1 = dA0 + 64 * 80;
    const uint32_t aLane = (uint32_t)((lane & 15) * 80 + (lane >> 4) * 16);
    const uint32_t bLane = (uint32_t)(((lane & 7) + ((lane >> 4) << 3)) * 80
                                      + (((lane >> 3) & 1) << 4));

    float acc[4][4][4] = {};

    auto load_chunk = [&](int kc, int buf) {
        uint32_t base = smb + (uint32_t)buf * 40960u;
        int kp = kc * 16 + lseg * 4;
        cpasync16(base + dA0, a0h + kp);
        cpasync16(base + dA1, a1h + kp);
        cpasync16(base + 10240u + dA0, a0l + kp);
        cpasync16(base + 10240u + dA1, a1l + kp);
        cpasync16(base + 20480u + dA0, b0h + kp);
        cpasync16(base + 20480u + dA1, b1h + kp);
        cpasync16(base + 30720u + dA0, b0l + kp);
        cpasync16(base + 30720u + dA1, b1l + kp);
        asm volatile("cp.async.commit_group;");
    };
    auto compute_chunk = [&](int buf) {
        uint32_t base = smb + (uint32_t)buf * 40960u;
        #pragma unroll
        for (int ks = 0; ks < 2; ks++) {
            uint32_t koff = (uint32_t)ks * 32;
            uint32_t ah[4][4], al[4][4], bh[2][4], bl[2][4];
            #pragma unroll
            for (int mi = 0; mi < 4; mi++) {
                uint32_t ra = base + (uint32_t)(wr * 64 + mi * 16) * 80 + aLane + koff;
                LDSM4(ah[mi], ra);
                LDSM4(al[mi], ra + 10240u);
            }
            #pragma unroll
            for (int np = 0; np < 2; np++) {
                uint32_t rb = base + 20480u + (uint32_t)(wc * 32 + np * 16) * 80 + bLane + koff;
                LDSM4(bh[np], rb);
                LDSM4(bl[np], rb + 10240u);
            }
            #pragma unroll
            for (int mi = 0; mi < 4; mi++)
                #pragma unroll
                for (int ni = 0; ni < 4; ni++) {
                    const int np = ni >> 1, s = (ni & 1) * 2;
                    MMA(acc[mi][ni], ah[mi], bh[np][s], bh[np][s + 1]);
                    MMA(acc[mi][ni], ah[mi], bl[np][s], bl[np][s + 1]);
                    MMA(acc[mi][ni], al[mi], bh[np][s], bh[np][s + 1]);
                }
        }
    };

    load_chunk(0, 0);
    #pragma unroll 1
    for (int kc = 0; kc < 8; kc++) {
        if (kc < 7) {
            load_chunk(kc + 1, (kc + 1) & 1);
            asm volatile("cp.async.wait_group 1;");
        } else {
            asm volatile("cp.async.wait_group 0;");
        }
        __syncthreads();
        compute_chunk(kc & 1);
        __syncthreads();
    }

    const int dir = bx >> 3;
    #pragma unroll
    for (int mi = 0; mi < 4; mi++) {
        const int r0 = by * 128 + wr * 64 + mi * 16 + (lane >> 2);
        #pragma unroll
        for (int ni = 0; ni < 4; ni++) {
            const int gcol = (bx & 7) * 128 + wc * 32 + ni * 8 + (lane & 3) * 2;
            if (r0 < VSZ)
                *(float2*)(g_XG + ((size_t)dir * VSZ + r0) * 1024 + gcol)
                    = make_float2(acc[mi][ni][0], acc[mi][ni][1]);
            if (r0 + 8 < VSZ)
                *(float2*)(g_XG + ((size_t)dir * VSZ + r0 + 8) * 1024 + gcol)
                    = make_float2(acc[mi][ni][2], acc[mi][ni][3]);
        }
    }
}

// ---------------------------------------------------------------------------
// Step kernel: preact = h @ Whh^T (K=256, split mma)  then fused epilogue:
// gates -> smem, + XG gather + bias, LSTM pointwise, h repack, c update,
// deterministic per-(dir,bx) row-sum accumulation.
// ---------------------------------------------------------------------------
__global__ __launch_bounds__(256)
void lstm_step_kernel(const void* __restrict__ neigh, int t) {
    extern __shared__ unsigned sm[];
    __shared__ float red[256];
    const uint32_t smb = smem_u32(sm);
    const int tid = threadIdx.x, lane = tid & 31, warp = tid >> 5;
    const int wr = warp >> 2, wc = warp & 3;
    const int bx = blockIdx.x, by = blockIdx.y, dir = blockIdx.z;
    const int t_x = dir ? (SLEN - 1 - t) : t;

    // token index for this thread's pointwise row (one row per thread pair)
    const int prow = tid & 127, phalf = tid >> 7;
    const int pn = by * 128 + prow;
    long long tok;
    if (g_is64) tok = ((const long long*)neigh)[(long long)pn * SLEN + t_x];
    else        tok = ((const int*)neigh)[pn * SLEN + t_x];

    const int lrow = tid >> 2, lseg = tid & 3;
    const int n0 = by * 128 + lrow, n1 = n0 + 64;
    const unsigned* a0h = g_Hhi + ((size_t)dir * NSEQ + n0) * 128;
    const unsigned* a1h = g_Hhi + ((size_t)dir * NSEQ + n1) * 128;
    const unsigned* a0l = g_Hlo + ((size_t)dir * NSEQ + n0) * 128;
    const unsigned* a1l = g_Hlo + ((size_t)dir * NSEQ + n1) * 128;
    const unsigned* b0h = g_WhhHi + (size_t)(dir * 1024 + bx * 128 + lrow) * 128;
    const unsigned* b1h = b0h + 64 * 128;
    const unsigned* b0l = g_WhhLo + (size_t)(dir * 1024 + bx * 128 + lrow) * 128;
    const unsigned* b1l = b0l + 64 * 128;

    const uint32_t dA0 = (uint32_t)(lrow * 20 + lseg * 4) * 4;
    const uint32_t dA1 = dA0 + 64 * 80;
    const uint32_t aLane = (uint32_t)((lane & 15) * 80 + (lane >> 4) * 16);
    const uint32_t bLane = (uint32_t)(((lane & 7) + ((lane >> 4) << 3)) * 80
                                      + (((lane >> 3) & 1) << 4));

    float acc[4][4][4] = {};

    auto load_chunk = [&](int kc, int buf) {
        uint32_t base = smb + (uint32_t)buf * 40960u;
        int kp = kc * 16 + lseg * 4;
        cpasync16(base + dA0, a0h + kp);
        cpasync16(base + dA1, a1h + kp);
        cpasync16(base + 10240u + dA0, a0l + kp);
        cpasync16(base + 10240u + dA1, a1l + kp);
        cpasync16(base + 20480u + dA0, b0h + kp);
        cpasync16(base + 20480u + dA1, b1h + kp);
        cpasync16(base + 30720u + dA0, b0l + kp);
        cpasync16(base + 30720u + dA1, b1l + kp);
        asm volatile("cp.async.commit_group;");
    };
    auto compute_chunk = [&](int buf) {
        uint32_t base = smb + (uint32_t)buf * 40960u;
        #pragma unroll
        for (int ks = 0; ks < 2; ks++) {
            uint32_t koff = (uint32_t)ks * 32;
            uint32_t ah[4][4], al[4][4], bh[2][4], bl[2][4];
            #pragma unroll
            for (int mi = 0; mi < 4; mi++) {
                uint32_t ra = base + (uint32_t)(wr * 64 + mi * 16) * 80 + aLane + koff;
                LDSM4(ah[mi], ra);
                LDSM4(al[mi], ra + 10240u);
            }
            #pragma unroll
            for (int np = 0; np < 2; np++) {
                uint32_t rb = base + 20480u + (uint32_t)(wc * 32 + np * 16) * 80 + bLane + koff;
                LDSM4(bh[np], rb);
                LDSM4(bl[np], rb + 10240u);
            }
            #pragma unroll
            for (int mi = 0; mi < 4; mi++)
                #pragma unroll
                for (int ni = 0; ni < 4; ni++) {
                    const int np = ni >> 1, s = (ni & 1) * 2;
                    MMA(acc[mi][ni], ah[mi], bh[np][s], bh[np][s + 1]);
                    MMA(acc[mi][ni], ah[mi], bl[np][s], bl[np][s + 1]);
                    MMA(acc[mi][ni], al[mi], bh[np][s], bh[np][s + 1]);
                }
        }
    };

    load_chunk(0, 0);
    #pragma unroll 1
    for (int kc = 0; kc < 8; kc++) {
        if (kc < 7) {
            load_chunk(kc + 1, (kc + 1) & 1);
            asm volatile("cp.async.wait_group 1;");
        } else {
            asm volatile("cp.async.wait_group 0;");
        }
        __syncthreads();
        compute_chunk(kc & 1);
        __syncthreads();
    }

    // ---- epilogue: acc -> smem (stride 132 floats) ----
    float* smg = (float*)sm;
    #pragma unroll
    for (int mi = 0; mi < 4; mi++) {
        const int r0 = wr * 64 + mi * 16 + (lane >> 2);
        #pragma unroll
        for (int ni = 0; ni < 4; ni++) {
            const int c = wc * 32 + ni * 8 + (lane & 3) * 2;
            smg[r0 * 132 + c]           = acc[mi][ni][0];
            smg[r0 * 132 + c + 1]       = acc[mi][ni][1];
            smg[(r0 + 8) * 132 + c]     = acc[mi][ni][2];
            smg[(r0 + 8) * 132 + c + 1] = acc[mi][ni][3];
        }
    }
    __syncthreads();

    // ---- pointwise: 2 threads per row, 16 units each ----
    {
        const float4* xg4 = (const float4*)(g_XG
            + ((size_t)dir * VSZ + (size_t)tok) * 1024 + bx * 128 + phalf * 64);
        const float4* bi4 = (const float4*)(g_biasI + dir * 1024 + bx * 128 + phalf * 64);
        float* cp = g_c + ((size_t)dir * NSEQ + pn) * 256 + bx * 32 + phalf * 16;
        unsigned* hhp = g_Hhi + ((size_t)dir * NSEQ + pn) * 128 + bx * 16 + phalf * 8;
        unsigned* hlp = g_Hlo + ((size_t)dir * NSEQ + pn) * 128 + bx * 16 + phalf * 8;

        float4 cc[4];
        #pragma unroll
        for (int q = 0; q < 4; q++) cc[q] = ((float4*)cp)[q];
        float* ccf = (float*)cc;

        float ssum = 0.0f, hv[16];
        #pragma unroll
        for (int q = 0; q < 16; q++) {
            float4 x = xg4[q];
            float4 bb = bi4[q];
            int c0 = prow * 132 + phalf * 64 + 4 * q;
            float gi = smg[c0 + 0] + x.x + bb.x;
            float gf = smg[c0 + 1] + x.y + bb.y;
            float gg = smg[c0 + 2] + x.z + bb.z;
            float go = smg[c0 + 3] + x.w + bb.w;
            float si = 1.0f / (1.0f + __expf(-gi));
            float sf = 1.0f / (1.0f + __expf(-gf));
            float so = 1.0f / (1.0f + __expf(-go));
            float cn = sf * ccf[q] + si * tanhf(gg);
            float hn = so * tanhf(cn);
            ccf[q] = cn;
            hv[q] = hn;
            ssum += hn;
        }
        #pragma unroll
        for (int q = 0; q < 4; q++) ((float4*)cp)[q] = cc[q];
        #pragma unroll
        for (int w = 0; w < 8; w++) {
            unsigned lo;
            unsigned hi = pack_split(hv[2 * w], hv[2 * w + 1], lo);
            hhp[w] = hi;
            hlp[w] = lo;
        }
        red[tid] = ssum;
    }
    __syncthreads();
    if (phalf == 0)
        g_part[(dir * 8 + bx) * NSEQ + pn] += red[tid] + red[tid + 128];
}

// ---------------------------------------------------------------------------
__global__ void final_acc_kernel() {
    int n = blockIdx.x * blockDim.x + threadIdx.x;
    if (n >= NSEQ) return;
    float s = 0.0f;
    #pragma unroll
    for (int p = 0; p < 16; p++) s += g_part[p * NSEQ + n];
    g_acc[n] = s * (1.0f / 512.0f);
}

__global__ void final_bcast_kernel(float* __restrict__ out) {
    int i = blockIdx.x * blockDim.x + threadIdx.x;
    if (i < NSEQ * 512) out[i] = g_acc[i >> 9];
}

// ---------------------------------------------------------------------------
extern "C" void kernel_launch(void* const* d_in, const int* in_sizes, int n_in,
                              void* d_out, int out_size) {
    const float* emb   = (const float*)d_in[0];
    const float* wih_f = (const float*)d_in[1];
    const float* whh_f = (const float*)d_in[2];
    const float* b_f   = (const float*)d_in[3];
    const float* wih_b = (const float*)d_in[4];
    const float* whh_b = (const float*)d_in[5];
    const float* b_b   = (const float*)d_in[6];
    const void*  neigh = d_in[7];
    float* out = (float*)d_out;

    cudaFuncSetAttribute(vocab_gemm_kernel,
                         cudaFuncAttributeMaxDynamicSharedMemorySize, 81920);
    cudaFuncSetAttribute(lstm_step_kernel,
                         cudaFuncAttributeMaxDynamicSharedMemorySize, 81920);

    detect_idx_kernel<<<1, 1>>>(neigh);
    {
        size_t tot = (size_t)VSZ * 128;
        prep_emb_kernel<<<(unsigned)((tot + 255) / 256), 256>>>(emb);
    }
    prep_w_kernel<<<(2048 * 128 + 255) / 256, 256>>>(wih_f, whh_f, wih_b, whh_b);
    {
        int tot = 2 * NSEQ * 256;
        prep_state_kernel<<<(tot + 255) / 256, 256>>>(b_f, b_b);
    }

    {
        dim3 grid(16, (VSZ + 127) / 128);   // (16, 782)
        vocab_gemm_kernel<<<grid, 256, 81920>>>();
    }

    dim3 sgrid(8, NSEQ / 128, 2);           // (8, 64, 2)
    for (int t = 0; t < SLEN; t++)
        lstm_step_kernel<<<sgrid, 256, 81920>>>(neigh, t);

    final_acc_kernel<<<(NSEQ + 255) / 256, 256>>>();
    final_bcast_kernel<<<(NSEQ * 512 + 255) / 256, 256>>>(out);
}

// round 8
// speedup vs baseline: 3.2631x; 1.2754x over previous
#include <cuda_runtime.h>
#include <cuda_fp16.h>
#include <cstdint>
#include <cstddef>

#define VSZ   100000
#define NSEQ  8192
#define SLEN  20

// ---------------------------------------------------------------------------
// Device globals. fp16 packed u32 (two k-consecutive halves). hi plane at
// word offset +0, lo plane at +128 within each 256-word row -> one base
// pointer per row, +128 folds into the instruction immediate.
// Gate columns INTERLEAVED: gcol = unit*4 + gate (i,f,g,o).
// ---------------------------------------------------------------------------
__device__ __align__(256) unsigned g_E[(size_t)VSZ * 256];      // 102 MB
__device__ __align__(256) unsigned g_Wih[2048 * 256];           // [dir*1024+gcol][hi|lo]
__device__ __align__(256) unsigned g_Whh[2048 * 256];
__device__ __align__(256) unsigned g_H[2 * NSEQ * 256];
__device__ __align__(256) float    g_c[2 * NSEQ * 256];
__device__ __align__(256) float    g_XG[(size_t)2 * VSZ * 1024];  // 819 MB
__device__ __align__(256) float    g_biasI[2048];
__device__ __align__(256) float    g_part[16 * NSEQ];
__device__ __align__(256) float    g_acc[NSEQ];
__device__ int g_is64;

// ---------------------------------------------------------------------------
__device__ __forceinline__ unsigned pack_split(float a, float b, unsigned& lo) {
    __half ha = __float2half_rn(a), hb = __float2half_rn(b);
    __half la = __float2half_rn(a - __half2float(ha));
    __half lb = __float2half_rn(b - __half2float(hb));
    lo = (unsigned)__half_as_ushort(la) | ((unsigned)__half_as_ushort(lb) << 16);
    return (unsigned)__half_as_ushort(ha) | ((unsigned)__half_as_ushort(hb) << 16);
}

__device__ __forceinline__ uint32_t smem_u32(const void* p) {
    uint32_t a;
    asm("{ .reg .u64 t; cvta.to.shared.u64 t, %1; cvt.u32.u64 %0, t; }" : "=r"(a) : "l"(p));
    return a;
}

__device__ __forceinline__ void cpasync16(uint32_t dst, const void* src) {
    asm volatile("cp.async.cg.shared.global [%0],[%1],16;" :: "r"(dst), "l"(src));
}

#define LDSM4(r, addr) asm volatile( \
    "ldmatrix.sync.aligned.m8n8.x4.shared.b16 {%0,%1,%2,%3},[%4];" \
    : "=r"((r)[0]), "=r"((r)[1]), "=r"((r)[2]), "=r"((r)[3]) : "r"(addr))

#define MMA(d, a, b0, b1) asm volatile( \
    "mma.sync.aligned.m16n8k16.row.col.f32.f16.f16.f32 " \
    "{%0,%1,%2,%3},{%4,%5,%6,%7},{%8,%9},{%0,%1,%2,%3};" \
    : "+f"((d)[0]), "+f"((d)[1]), "+f"((d)[2]), "+f"((d)[3]) \
    : "r"((a)[0]), "r"((a)[1]), "r"((a)[2]), "r"((a)[3]), "r"(b0), "r"(b1))

// ---------------------------------------------------------------------------
// Prep: emb split (hi|lo interleaved per row).
// ---------------------------------------------------------------------------
__global__ void prep_emb_kernel(const float* __restrict__ emb) {
    size_t i = (size_t)blockIdx.x * blockDim.x + threadIdx.x;
    if (i >= (size_t)VSZ * 128) return;
    size_t v = i >> 7;
    int p = (int)(i & 127);
    unsigned lo;
    unsigned hi = pack_split(emb[v * 256 + 2 * p], emb[v * 256 + 2 * p + 1], lo);
    g_E[v * 256 + p]       = hi;
    g_E[v * 256 + 128 + p] = lo;
}

// Interleaved weight split: row = dir*1024 + (unit*4+gate); orig torch row =
// gate*256 + unit; K halves paired; hi at +0, lo at +128.
__global__ void prep_w_kernel(const float* __restrict__ wihf,
                              const float* __restrict__ whhf,
                              const float* __restrict__ wihb,
                              const float* __restrict__ whhb) {
    int i = blockIdx.x * blockDim.x + threadIdx.x;
    if (i >= 2048 * 128) return;
    int dirgcol = i >> 7, kp = i & 127;
    int dir = dirgcol >> 10, gcol = dirgcol & 1023;
    int orow = (gcol & 3) * 256 + (gcol >> 2);
    const float* wih = dir ? wihb : wihf;
    const float* whh = dir ? whhb : whhf;
    unsigned lo, hi;
    hi = pack_split(wih[orow * 256 + 2 * kp], wih[orow * 256 + 2 * kp + 1], lo);
    g_Wih[dirgcol * 256 + kp]       = hi;
    g_Wih[dirgcol * 256 + 128 + kp] = lo;
    hi = pack_split(whh[orow * 256 + 2 * kp], whh[orow * 256 + 2 * kp + 1], lo);
    g_Whh[dirgcol * 256 + kp]       = hi;
    g_Whh[dirgcol * 256 + 128 + kp] = lo;
}

// state zero + interleaved bias + idx dtype detect, one launch
__global__ void prep_state_kernel(const float* __restrict__ bf,
                                  const float* __restrict__ bb,
                                  const void* __restrict__ neigh) {
    int i = blockIdx.x * blockDim.x + threadIdx.x;
    if (i < 2 * NSEQ * 256) { g_H[i] = 0u; g_c[i] = 0.0f; }
    if (i < 16 * NSEQ)      g_part[i] = 0.0f;
    if (i < 2048) {
        int dir = i >> 10, gcol = i & 1023;
        const float* b = dir ? bb : bf;
        g_biasI[i] = b[(gcol & 3) * 256 + (gcol >> 2)];
    }
    if (i == 0) {
        const long long* p = (const long long*)neigh;
        int ok = 1;
        #pragma unroll
        for (int q = 0; q < 4; q++) {
            long long v = p[q];
            if (v < 0 || v >= (long long)VSZ) ok = 0;
        }
        g_is64 = ok;
    }
}

// ---------------------------------------------------------------------------
// Vocab GEMM: XG[dir][v][gcol] = sum_k emb[v][k]*Wih[dir][gcol][k]
// 128x128, K=256 (8 chunks of 32 halves), cp.async double buffered, 2 CTA/SM.
// smem plane = 128 rows * 20 u32 (16 payload + 4 pad); buffer = 4 planes.
// ---------------------------------------------------------------------------
__global__ __launch_bounds__(256, 2)
void vocab_gemm_kernel() {
    extern __shared__ unsigned sm[];
    const uint32_t smb = smem_u32(sm);
    const int tid = threadIdx.x, lane = tid & 31, warp = tid >> 5;
    const int wr = warp >> 2, wc = warp & 3;
    const int bx = blockIdx.x, by = blockIdx.y;

    const int lrow = tid >> 2, lseg = tid & 3;
    int v0 = by * 128 + lrow, v1 = v0 + 64;
    if (v0 >= VSZ) v0 = VSZ - 1;
    if (v1 >= VSZ) v1 = VSZ - 1;
    const unsigned* pA0 = g_E + (size_t)v0 * 256;
    const unsigned* pA1 = g_E + (size_t)v1 * 256;
    const unsigned* pB0 = g_Wih + (size_t)(bx * 128 + lrow) * 256;
    const unsigned* pB1 = pB0 + 64 * 256;

    const uint32_t dA0 = (uint32_t)(lrow * 20 + lseg * 4) * 4;
    const uint32_t dA1 = dA0 + 64 * 80;
    const uint32_t aLane = (uint32_t)((lane & 15) * 80 + (lane >> 4) * 16);
    const uint32_t bLane = (uint32_t)(((lane & 7) + ((lane >> 4) << 3)) * 80
                                      + (((lane >> 3) & 1) << 4));

    float acc[4][4][4] = {};

    auto load_chunk = [&](int kc, int buf) {
        uint32_t base = smb + (uint32_t)buf * 40960u;
        int kp = kc * 16 + lseg * 4;
        cpasync16(base + dA0,           pA0 + kp);
        cpasync16(base + dA1,           pA1 + kp);
        cpasync16(base + 10240u + dA0,  pA0 + 128 + kp);
        cpasync16(base + 10240u + dA1,  pA1 + 128 + kp);
        cpasync16(base + 20480u + dA0,  pB0 + kp);
        cpasync16(base + 20480u + dA1,  pB1 + kp);
        cpasync16(base + 30720u + dA0,  pB0 + 128 + kp);
        cpasync16(base + 30720u + dA1,  pB1 + 128 + kp);
        asm volatile("cp.async.commit_group;");
    };
    auto compute_chunk = [&](int buf) {
        uint32_t base = smb + (uint32_t)buf * 40960u;
        #pragma unroll
        for (int ks = 0; ks < 2; ks++) {
            uint32_t koff = (uint32_t)ks * 32;
            uint32_t ah[4][4], al[4][4], bh[2][4], bl[2][4];
            #pragma unroll
            for (int mi = 0; mi < 4; mi++) {
                uint32_t ra = base + (uint32_t)(wr * 64 + mi * 16) * 80 + aLane + koff;
                LDSM4(ah[mi], ra);
                LDSM4(al[mi], ra + 10240u);
            }
            #pragma unroll
            for (int np = 0; np < 2; np++) {
                uint32_t rb = base + 20480u + (uint32_t)(wc * 32 + np * 16) * 80 + bLane + koff;
                LDSM4(bh[np], rb);
                LDSM4(bl[np], rb + 10240u);
            }
            #pragma unroll
            for (int mi = 0; mi < 4; mi++)
                #pragma unroll
                for (int ni = 0; ni < 4; ni++) {
                    const int np = ni >> 1, s = (ni & 1) * 2;
                    MMA(acc[mi][ni], ah[mi], bh[np][s], bh[np][s + 1]);
                    MMA(acc[mi][ni], ah[mi], bl[np][s], bl[np][s + 1]);
                    MMA(acc[mi][ni], al[mi], bh[np][s], bh[np][s + 1]);
                }
        }
    };

    load_chunk(0, 0);
    #pragma unroll 1
    for (int kc = 0; kc < 8; kc++) {
        if (kc < 7) {
            load_chunk(kc + 1, (kc + 1) & 1);
            asm volatile("cp.async.wait_group 1;");
        } else {
            asm volatile("cp.async.wait_group 0;");
        }
        __syncthreads();
        compute_chunk(kc & 1);
        __syncthreads();
    }

    const int dir = bx >> 3;
    #pragma unroll
    for (int mi = 0; mi < 4; mi++) {
        const int r0 = by * 128 + wr * 64 + mi * 16 + (lane >> 2);
        #pragma unroll
        for (int ni = 0; ni < 4; ni++) {
            const int gcol = (bx & 7) * 128 + wc * 32 + ni * 8 + (lane & 3) * 2;
            if (r0 < VSZ)
                *(float2*)(g_XG + ((size_t)dir * VSZ + r0) * 1024 + gcol)
                    = make_float2(acc[mi][ni][0], acc[mi][ni][1]);
            if (r0 + 8 < VSZ)
                *(float2*)(g_XG + ((size_t)dir * VSZ + r0 + 8) * 1024 + gcol)
                    = make_float2(acc[mi][ni][2], acc[mi][ni][3]);
        }
    }
}

// ---------------------------------------------------------------------------
// Step kernel: preact = h @ Whh^T (K=256 split mma), fused epilogue:
// acc -> smem, + XG gather + bias, LSTM pointwise, h repack, c update,
// deterministic per-(dir,bx) partial row sums.
// ---------------------------------------------------------------------------
__global__ __launch_bounds__(256, 2)
void lstm_step_kernel(const void* __restrict__ neigh, int t) {
    extern __shared__ unsigned sm[];
    __shared__ float red[256];
    const uint32_t smb = smem_u32(sm);
    const int tid = threadIdx.x, lane = tid & 31, warp = tid >> 5;
    const int wr = warp >> 2, wc = warp & 3;
    const int bx = blockIdx.x, by = blockIdx.y, dir = blockIdx.z;
    const int t_x = dir ? (SLEN - 1 - t) : t;

    const int prow = tid & 127, phalf = tid >> 7;
    const int pn = by * 128 + prow;
    long long tok;
    if (g_is64) tok = ((const long long*)neigh)[(long long)pn * SLEN + t_x];
    else        tok = ((const int*)neigh)[pn * SLEN + t_x];

    const int lrow = tid >> 2, lseg = tid & 3;
    const int n0 = by * 128 + lrow;
    const unsigned* pA0 = g_H + ((size_t)dir * NSEQ + n0) * 256;
    const unsigned* pA1 = pA0 + 64 * 256;
    const unsigned* pB0 = g_Whh + (size_t)(dir * 1024 + bx * 128 + lrow) * 256;
    const unsigned* pB1 = pB0 + 64 * 256;

    const uint32_t dA0 = (uint32_t)(lrow * 20 + lseg * 4) * 4;
    const uint32_t dA1 = dA0 + 64 * 80;
    const uint32_t aLane = (uint32_t)((lane & 15) * 80 + (lane >> 4) * 16);
    const uint32_t bLane = (uint32_t)(((lane & 7) + ((lane >> 4) << 3)) * 80
                                      + (((lane >> 3) & 1) << 4));

    float acc[4][4][4] = {};

    auto load_chunk = [&](int kc, int buf) {
        uint32_t base = smb + (uint32_t)buf * 40960u;
        int kp = kc * 16 + lseg * 4;
        cpasync16(base + dA0,           pA0 + kp);
        cpasync16(base + dA1,           pA1 + kp);
        cpasync16(base + 10240u + dA0,  pA0 + 128 + kp);
        cpasync16(base + 10240u + dA1,  pA1 + 128 + kp);
        cpasync16(base + 20480u + dA0,  pB0 + kp);
        cpasync16(base + 20480u + dA1,  pB1 + kp);
        cpasync16(base + 30720u + dA0,  pB0 + 128 + kp);
        cpasync16(base + 30720u + dA1,  pB1 + 128 + kp);
        asm volatile("cp.async.commit_group;");
    };
    auto compute_chunk = [&](int buf) {
        uint32_t base = smb + (uint32_t)buf * 40960u;
        #pragma unroll
        for (int ks = 0; ks < 2; ks++) {
            uint32_t koff = (uint32_t)ks * 32;
            uint32_t ah[4][4], al[4][4], bh[2][4], bl[2][4];
            #pragma unroll
            for (int mi = 0; mi < 4; mi++) {
                uint32_t ra = base + (uint32_t)(wr * 64 + mi * 16) * 80 + aLane + koff;
                LDSM4(ah[mi], ra);
                LDSM4(al[mi], ra + 10240u);
            }
            #pragma unroll
            for (int np = 0; np < 2; np++) {
                uint32_t rb = base + 20480u + (uint32_t)(wc * 32 + np * 16) * 80 + bLane + koff;
                LDSM4(bh[np], rb);
                LDSM4(bl[np], rb + 10240u);
            }
            #pragma unroll
            for (int mi = 0; mi < 4; mi++)
                #pragma unroll
                for (int ni = 0; ni < 4; ni++) {
                    const int np = ni >> 1, s = (ni & 1) * 2;
                    MMA(acc[mi][ni], ah[mi], bh[np][s], bh[np][s + 1]);
                    MMA(acc[mi][ni], ah[mi], bl[np][s], bl[np][s + 1]);
                    MMA(acc[mi][ni], al[mi], bh[np][s], bh[np][s + 1]);
                }
        }
    };

    load_chunk(0, 0);
    #pragma unroll 1
    for (int kc = 0; kc < 8; kc++) {
        if (kc < 7) {
            load_chunk(kc + 1, (kc + 1) & 1);
            asm volatile("cp.async.wait_group 1;");
        } else {
            asm volatile("cp.async.wait_group 0;");
        }
        __syncthreads();
        compute_chunk(kc & 1);
        __syncthreads();
    }

    // ---- epilogue: acc -> smem (row stride 132 floats) ----
    float* smg = (float*)sm;
    #pragma unroll
    for (int mi = 0; mi < 4; mi++) {
        const int r0 = wr * 64 + mi * 16 + (lane >> 2);
        #pragma unroll
        for (int ni = 0; ni < 4; ni++) {
            const int c = wc * 32 + ni * 8 + (lane & 3) * 2;
            smg[r0 * 132 + c]           = acc[mi][ni][0];
            smg[r0 * 132 + c + 1]       = acc[mi][ni][1];
            smg[(r0 + 8) * 132 + c]     = acc[mi][ni][2];
            smg[(r0 + 8) * 132 + c + 1] = acc[mi][ni][3];
        }
    }
    __syncthreads();

    // ---- pointwise: 2 threads per row, 16 units each ----
    {
        const float4* xg4 = (const float4*)(g_XG
            + ((size_t)dir * VSZ + (size_t)tok) * 1024 + bx * 128 + phalf * 64);
        const float4* bi4 = (const float4*)(g_biasI + dir * 1024 + bx * 128 + phalf * 64);
        float* cp = g_c + ((size_t)dir * NSEQ + pn) * 256 + bx * 32 + phalf * 16;
        unsigned* hp = g_H + ((size_t)dir * NSEQ + pn) * 256 + bx * 16 + phalf * 8;

        float4 cc[4];
        #pragma unroll
        for (int q = 0; q < 4; q++) cc[q] = ((float4*)cp)[q];
        float* ccf = (float*)cc;

        float ssum = 0.0f, hv[16];
        #pragma unroll
        for (int q = 0; q < 16; q++) {
            float4 x = xg4[q];
            float4 bb = bi4[q];
            int c0 = prow * 132 + phalf * 64 + 4 * q;
            float gi = smg[c0 + 0] + x.x + bb.x;
            float gf = smg[c0 + 1] + x.y + bb.y;
            float gg = smg[c0 + 2] + x.z + bb.z;
            float go = smg[c0 + 3] + x.w + bb.w;
            float si = 1.0f / (1.0f + __expf(-gi));
            float sf = 1.0f / (1.0f + __expf(-gf));
            float so = 1.0f / (1.0f + __expf(-go));
            float cn = sf * ccf[q] + si * tanhf(gg);
            float hn = so * tanhf(cn);
            ccf[q] = cn;
            hv[q] = hn;
            ssum += hn;
        }
        #pragma unroll
        for (int q = 0; q < 4; q++) ((float4*)cp)[q] = cc[q];
        #pragma unroll
        for (int w = 0; w < 8; w++) {
            unsigned lo;
            unsigned hi = pack_split(hv[2 * w], hv[2 * w + 1], lo);
            hp[w]       = hi;
            hp[w + 128] = lo;
        }
        red[tid] = ssum;
    }
    __syncthreads();
    if (phalf == 0)
        g_part[(dir * 8 + bx) * NSEQ + pn] += red[tid] + red[tid + 128];
}

// ---------------------------------------------------------------------------
__global__ void final_acc_kernel() {
    int n = blockIdx.x * blockDim.x + threadIdx.x;
    if (n >= NSEQ) return;
    float s = 0.0f;
    #pragma unroll
    for (int p = 0; p < 16; p++) s += g_part[p * NSEQ + n];
    g_acc[n] = s * (1.0f / 512.0f);
}

__global__ void final_bcast_kernel(float* __restrict__ out) {
    int i = blockIdx.x * blockDim.x + threadIdx.x;
    if (i < NSEQ * 512) out[i] = g_acc[i >> 9];
}

// ---------------------------------------------------------------------------
extern "C" void kernel_launch(void* const* d_in, const int* in_sizes, int n_in,
                              void* d_out, int out_size) {
    const float* emb   = (const float*)d_in[0];
    const float* wih_f = (const float*)d_in[1];
    const float* whh_f = (const float*)d_in[2];
    const float* b_f   = (const float*)d_in[3];
    const float* wih_b = (const float*)d_in[4];
    const float* whh_b = (const float*)d_in[5];
    const float* b_b   = (const float*)d_in[6];
    const void*  neigh = d_in[7];
    float* out = (float*)d_out;

    cudaFuncSetAttribute(vocab_gemm_kernel,
                         cudaFuncAttributeMaxDynamicSharedMemorySize, 81920);
    cudaFuncSetAttribute(lstm_step_kernel,
                         cudaFuncAttributeMaxDynamicSharedMemorySize, 81920);

    {
        size_t tot = (size_t)VSZ * 128;
        prep_emb_kernel<<<(unsigned)((tot + 255) / 256), 256>>>(emb);
    }
    prep_w_kernel<<<(2048 * 128 + 255) / 256, 256>>>(wih_f, whh_f, wih_b, whh_b);
    {
        int tot = 2 * NSEQ * 256;
        prep_state_kernel<<<(tot + 255) / 256, 256>>>(b_f, b_b, neigh);
    }

    {
        dim3 grid(16, (VSZ + 127) / 128);   // (16, 782)
        vocab_gemm_kernel<<<grid, 256, 81920>>>();
    }

    dim3 sgrid(8, NSEQ / 128, 2);           // (8, 64, 2)
    for (int t = 0; t < SLEN; t++)
        lstm_step_kernel<<<sgrid, 256, 81920>>>(neigh, t);

    final_acc_kernel<<<(NSEQ + 255) / 256, 256>>>();
    final_bcast_kernel<<<(NSEQ * 512 + 255) / 256, 256>>>(out);
}